// round 9
// baseline (speedup 1.0000x reference)
#include <cuda_runtime.h>
#include <cuda_bf16.h>
#include <cuda_fp16.h>
#include <float.h>
#include <stdint.h>

#define D_DIM   64
#define K_CODES 512
#define BLOCK   512          // 16 warps: 8 row-groups x 2 n-halves
#define GRID    148
#define NROWS   65536
#define NTILES  512          // 128 rows per tile
#define CAP     32           // worklist slots per row

// ---- SMEM layout (bytes) ----
#define SM_BH    0            // 8192 uint2 hi-bf16 B fragments (64KB)
#define SM_EST   65536        // est matrix: 128 rows x 520 halves (133120B)
#define EST_STRIDE 520
#define SM_SN    198656       // 512 floats: exact ||e_k||^2
#define SM_SMIN  200704       // 256 floats: per-half row min est
#define SM_SXN   201728       // 128 floats: ||x_r||^2
#define SM_SRX   202240       // 128 floats: ||x_r - xh_r||^2
#define SM_RCNT  202752       // 128 ints: per-row candidate count
#define SM_RBEST 203264       // 128 u64: per-row packed (dist,k)
#define SM_WL    204288       // 128*CAP ints: candidate k lists (16KB)
#define SM_SE2   220672       // int: max_k ||e-eh||^2 (bits)
#define SM_SH2   220676       // int: max_k ||eh||^2 (bits)
#define SM_LS    220680       // 16 doubles
#define SMEM_TOTAL 220808

__device__ float        g_embT[K_CODES * D_DIM];   // exact fp32 codebook [k][d]
__device__ double       g_partial[GRID];
__device__ unsigned int g_cnt = 0;

#define MMA(acc, a, b0, b1)                                                     \
    asm volatile(                                                               \
        "mma.sync.aligned.m16n8k16.row.col.f32.bf16.bf16.f32 "                  \
        "{%0,%1,%2,%3}, {%4,%5,%6,%7}, {%8,%9}, {%0,%1,%2,%3};"                 \
        : "+f"((acc)[0]), "+f"((acc)[1]), "+f"((acc)[2]), "+f"((acc)[3])        \
        : "r"((a)[0]), "r"((a)[1]), "r"((a)[2]), "r"((a)[3]), "r"(b0), "r"(b1))

__device__ __forceinline__ uint32_t pack_bf2(float a, float b) {
    return (uint32_t)__bfloat16_as_ushort(__float2bfloat16(a))
         | ((uint32_t)__bfloat16_as_ushort(__float2bfloat16(b)) << 16);
}

// exact fp32 squared distance row(x) vs code k (fixed summation order)
__device__ __forceinline__ float exact_dist(const float* __restrict__ xrow, int k) {
    const float4* xp = (const float4*)xrow;
    const float4* ep = (const float4*)(g_embT + k * D_DIM);
    float s = 0.f;
    #pragma unroll
    for (int j = 0; j < 16; j++) {
        float4 a = xp[j];
        float4 b = ep[j];
        float dx = a.x - b.x, dy = a.y - b.y, dz = a.z - b.z, dw = a.w - b.w;
        s = fmaf(dx, dx, s); s = fmaf(dy, dy, s);
        s = fmaf(dz, dz, s); s = fmaf(dw, dw, s);
    }
    return s;
}

__global__ void __launch_bounds__(BLOCK, 1)
vq_2stage(const float* __restrict__ x, const float* __restrict__ emb,
          float* __restrict__ out, int write_loss)
{
    extern __shared__ char smem[];
    uint2*              sBH   = (uint2*)(smem + SM_BH);
    __half*             sEst  = (__half*)(smem + SM_EST);
    float*              snm   = (float*)(smem + SM_SN);
    float*              smin  = (float*)(smem + SM_SMIN);
    float*              sxn   = (float*)(smem + SM_SXN);
    float*              srx   = (float*)(smem + SM_SRX);
    int*                rcnt  = (int*)(smem + SM_RCNT);
    unsigned long long* rbest = (unsigned long long*)(smem + SM_RBEST);
    int*                swl   = (int*)(smem + SM_WL);
    int*                sSE2  = (int*)(smem + SM_SE2);
    int*                sSH2  = (int*)(smem + SM_SH2);
    double*             sls   = (double*)(smem + SM_LS);

    const int tid  = threadIdx.x;
    const int w    = tid >> 5;
    const int lane = tid & 31;
    const int g    = lane >> 2;
    const int c    = lane & 3;
    const int rg   = w & 7;      // row-group (16 rows)
    const int nh   = w >> 3;     // n-half: codes [nh*256, +256)

    if (tid < 2) { sSE2[0] = 0; sSH2[0] = 0; }
    __syncthreads();

    // ---- Prologue 1: hi-bf16 B fragments + exact fp32 transpose ----
    for (int i = tid; i < 8192; i += BLOCK) {
        int nt = i >> 7;
        int ks = (i >> 5) & 3;
        int ln = i & 31;
        int fg = ln >> 2, fc = ln & 3;
        int n  = nt * 8 + fg;
        int d0 = ks * 16 + fc * 2;
        float e00 = __ldg(emb + (d0 + 0) * K_CODES + n);
        float e01 = __ldg(emb + (d0 + 1) * K_CODES + n);
        float e10 = __ldg(emb + (d0 + 8) * K_CODES + n);
        float e11 = __ldg(emb + (d0 + 9) * K_CODES + n);
        sBH[i] = make_uint2(pack_bf2(e00, e01), pack_bf2(e10, e11));
        g_embT[n * D_DIM + d0]     = e00;
        g_embT[n * D_DIM + d0 + 1] = e01;
        g_embT[n * D_DIM + d0 + 8] = e10;
        g_embT[n * D_DIM + d0 + 9] = e11;
    }
    // ---- Prologue 2: exact code norms + split-error maxima ----
    {
        const int k = tid;   // 512 == BLOCK
        float sn = 0.f, se = 0.f, sh = 0.f;
        #pragma unroll 8
        for (int d = 0; d < D_DIM; d++) {
            float v = emb[d * K_CODES + k];
            float h = __bfloat162float(__float2bfloat16(v));
            float r = v - h;
            sn = fmaf(v, v, sn);
            se = fmaf(r, r, se);
            sh = fmaf(h, h, sh);
        }
        snm[k] = sn;
        atomicMax(sSE2, __float_as_int(se));   // nonneg: int cmp == float cmp
        atomicMax(sSH2, __float_as_int(sh));
    }
    __syncthreads();

    const float S_e = sqrtf(__int_as_float(*sSE2)) * 1.0001f;  // max ||e-eh||
    const float S_h = sqrtf(__int_as_float(*sSH2)) * 1.0001f;  // max ||eh||

    double lacc = 0.0;

    for (int tile = blockIdx.x; tile < NTILES; tile += GRID) {
        const int rbase = tile * 128 + rg * 16 + g;

        // per-tile state init (no readers until after sync1)
        if (tid < 128) { rcnt[tid] = 0; rbest[tid] = ~0ull; }

        // ---- A fragments (hi split) + per-row norm / residual-norm ----
        uint32_t Ah[4][4];
        float xn0 = 0.f, xn1 = 0.f, rx0 = 0.f, rx1 = 0.f;
        {
            const float* xr0 = x + (size_t)rbase * D_DIM;
            const float* xr1 = xr0 + 8 * D_DIM;
            #pragma unroll
            for (int ks = 0; ks < 4; ks++) {
                #pragma unroll
                for (int p = 0; p < 2; p++) {
                    int col = 2 * c + 8 * p + 16 * ks;
                    float2 v0 = *(const float2*)(xr0 + col);
                    float2 v1 = *(const float2*)(xr1 + col);
                    xn0 = fmaf(v0.x, v0.x, fmaf(v0.y, v0.y, xn0));
                    xn1 = fmaf(v1.x, v1.x, fmaf(v1.y, v1.y, xn1));
                    float h0x = __bfloat162float(__float2bfloat16(v0.x));
                    float h0y = __bfloat162float(__float2bfloat16(v0.y));
                    float h1x = __bfloat162float(__float2bfloat16(v1.x));
                    float h1y = __bfloat162float(__float2bfloat16(v1.y));
                    float r0x = v0.x - h0x, r0y = v0.y - h0y;
                    float r1x = v1.x - h1x, r1y = v1.y - h1y;
                    rx0 = fmaf(r0x, r0x, fmaf(r0y, r0y, rx0));
                    rx1 = fmaf(r1x, r1x, fmaf(r1y, r1y, rx1));
                    Ah[ks][2 * p]     = pack_bf2(v0.x, v0.y);
                    Ah[ks][2 * p + 1] = pack_bf2(v1.x, v1.y);
                }
            }
        }
        #pragma unroll
        for (int off = 1; off <= 2; off <<= 1) {
            xn0 += __shfl_xor_sync(0xffffffffu, xn0, off);
            xn1 += __shfl_xor_sync(0xffffffffu, xn1, off);
            rx0 += __shfl_xor_sync(0xffffffffu, rx0, off);
            rx1 += __shfl_xor_sync(0xffffffffu, rx1, off);
        }
        if (c == 0 && nh == 0) {
            const int r = rg * 16 + g;
            sxn[r] = xn0;  sxn[r + 8] = xn1;
            srx[r] = rx0;  srx[r + 8] = rx1;
        }

        // ---- Stage A: estimated distances (hi-hi term), fp16 store + row min ----
        float m0 = FLT_MAX, m1 = FLT_MAX;
        const int ntbeg = nh * 32;
        #pragma unroll 1
        for (int nt0 = ntbeg; nt0 < ntbeg + 32; nt0 += 4) {
            float acc[4][4];
            #pragma unroll
            for (int u = 0; u < 4; u++)
                #pragma unroll
                for (int r = 0; r < 4; r++) acc[u][r] = 0.f;

            #pragma unroll
            for (int ks = 0; ks < 4; ks++)
                #pragma unroll
                for (int u = 0; u < 4; u++) {
                    uint2 b = sBH[((nt0 + u) * 4 + ks) * 32 + lane];
                    MMA(acc[u], Ah[ks], b.x, b.y);
                }

            #pragma unroll
            for (int u = 0; u < 4; u++) {
                const int kb = (nt0 + u) * 8 + 2 * c;
                float2 s2 = *(const float2*)(snm + kb);
                float e00 = fmaf(-2.f, acc[u][0], s2.x);
                float e01 = fmaf(-2.f, acc[u][1], s2.y);
                float e10 = fmaf(-2.f, acc[u][2], s2.x);
                float e11 = fmaf(-2.f, acc[u][3], s2.y);
                m0 = fminf(m0, fminf(e00, e01));
                m1 = fminf(m1, fminf(e10, e11));
                const int r0 = rg * 16 + g;
                *(__half2*)(sEst + r0 * EST_STRIDE + kb)       = __floats2half2_rn(e00, e01);
                *(__half2*)(sEst + (r0 + 8) * EST_STRIDE + kb) = __floats2half2_rn(e10, e11);
            }
        }
        #pragma unroll
        for (int off = 1; off <= 2; off <<= 1) {
            m0 = fminf(m0, __shfl_xor_sync(0xffffffffu, m0, off));
            m1 = fminf(m1, __shfl_xor_sync(0xffffffffu, m1, off));
        }
        if (c == 0) {
            const int r = rg * 16 + g;
            smin[nh * 128 + r]     = m0;
            smin[nh * 128 + r + 8] = m1;
        }
        __syncthreads();   // sync1: est, smin, norms, rcnt/rbest ready

        // ---- Scan: 4 threads per row, packed fp16 compares, append ----
        {
            const int srow = tid >> 2;
            const int sc   = tid & 3;
            float minest = fminf(smin[srow], smin[128 + srow]);
            float xns = sqrtf(sxn[srow]), rxs = sqrtf(srx[srow]);
            // rigorous: |est-true| <= 2(||dx||*||e|| + ||xh||*||de||)
            //   <= 2( rxs*(S_h+S_e) + (xns+rxs)*S_e ) = bnd
            float bnd  = 2.f * (rxs * (S_h + S_e) + (xns + rxs) * S_e);
            float thrf = minest + 2.f * bnd + 0.15f;         // +slack: fp16/accum rounding
            const __half2 thr2 = __float2half2_rn(thrf + 0.05f);  // round-up guard
            const __half2 zero2 = __float2half2_rn(0.f);
            const __half2* erow = (const __half2*)(sEst + srow * EST_STRIDE) + sc * 64;
            #pragma unroll 4
            for (int j = 0; j < 64; j++) {
                __half2 le = __hle2(erow[j], thr2);
                if (!__hbeq2(le, zero2)) {       // any half passed
                    float2 lf = __half22float2(le);
                    int k0 = sc * 128 + 2 * j;
                    if (lf.x != 0.f) {
                        int s = atomicAdd(&rcnt[srow], 1);
                        if (s < CAP) swl[srow * CAP + s] = k0;
                    }
                    if (lf.y != 0.f) {
                        int s = atomicAdd(&rcnt[srow], 1);
                        if (s < CAP) swl[srow * CAP + s] = k0 + 1;
                    }
                }
            }
        }
        __syncthreads();   // sync2: worklists complete

        // ---- Rescore: 1 candidate per thread, exact fp32, atomicMin pack ----
        #pragma unroll 1
        for (int idx = tid; idx < 128 * CAP; idx += BLOCK) {
            const int row  = idx >> 5;
            const int slot = idx & (CAP - 1);
            int cnt = rcnt[row]; if (cnt > CAP) cnt = CAP;
            if (slot < cnt) {
                const int k = swl[row * CAP + slot];
                float s = exact_dist(x + (size_t)(tile * 128 + row) * D_DIM, k);
                unsigned long long key =
                    ((unsigned long long)(unsigned)__float_as_int(s) << 32) | (unsigned)k;
                atomicMin(&rbest[row], key);
            }
        }
        // overflow fallback (provably correct; practically never taken)
        #pragma unroll 1
        for (int row = w; row < 128; row += 16) {
            if (rcnt[row] > CAP) {
                const float* xrow = x + (size_t)(tile * 128 + row) * D_DIM;
                for (int k = lane; k < K_CODES; k += 32) {
                    float s = exact_dist(xrow, k);
                    unsigned long long key =
                        ((unsigned long long)(unsigned)__float_as_int(s) << 32) | (unsigned)k;
                    atomicMin(&rbest[row], key);
                }
            }
        }
        __syncthreads();   // sync3: rbest final

        // ---- output + loss ----
        {
            const int r = tid >> 2;
            const int q = tid & 3;
            unsigned long long key = rbest[r];
            const int k = (int)(unsigned)key;
            if (q == 0) lacc += (double)__int_as_float((int)(key >> 32));
            const float4* src = (const float4*)(g_embT + k * D_DIM) + q * 4;
            float4* dst = (float4*)(out + (size_t)(tile * 128 + r) * D_DIM) + q * 4;
            dst[0] = src[0]; dst[1] = src[1]; dst[2] = src[2]; dst[3] = src[3];
        }
        __syncthreads();   // sync4: est/rbest reused next tile
    }

    // ---- loss: warp reduce -> CTA partial -> last block finalizes ----
    #pragma unroll
    for (int off = 16; off > 0; off >>= 1)
        lacc += __shfl_down_sync(0xffffffffu, lacc, off);
    if (lane == 0) sls[w] = lacc;
    __syncthreads();
    if (tid == 0) {
        double t = 0.0;
        #pragma unroll
        for (int i = 0; i < 16; i++) t += sls[i];
        g_partial[blockIdx.x] = t;
        __threadfence();
        unsigned n = atomicAdd(&g_cnt, 1u);
        if (n == GRID - 1) {
            __threadfence();
            double tot = 0.0;
            for (int i = 0; i < GRID; i++) tot += g_partial[i];
            if (write_loss)
                out[(size_t)NROWS * D_DIM] =
                    (float)(tot * (1.25 / ((double)NROWS * (double)D_DIM)));
            g_cnt = 0;   // reset for next graph replay
        }
    }
}

extern "C" void kernel_launch(void* const* d_in, const int* in_sizes, int n_in,
                              void* d_out, int out_size)
{
    const float* x   = (const float*)d_in[0];
    const float* emb = (const float*)d_in[1];
    float* out = (float*)d_out;

    const int write_loss = (out_size > NROWS * D_DIM) ? 1 : 0;

    static int configured = 0;
    if (!configured) {
        cudaFuncSetAttribute(vq_2stage, cudaFuncAttributeMaxDynamicSharedMemorySize, SMEM_TOTAL);
        configured = 1;
    }
    vq_2stage<<<GRID, BLOCK, SMEM_TOTAL>>>(x, emb, out, write_loss);
}

// round 10
// speedup vs baseline: 1.1098x; 1.1098x over previous
#include <cuda_runtime.h>
#include <cuda_bf16.h>
#include <cuda_fp16.h>
#include <float.h>
#include <stdint.h>

#define D_DIM   64
#define K_CODES 512
#define BLOCK   512          // 16 warps: 8 row-groups x 2 n-halves
#define GRID    148
#define NROWS   65536
#define NTILES  512          // 128 rows per tile
#define CAP     16           // worklist slots per row

// ---- SMEM layout (bytes) ----
#define SM_BH    0            // 8192 uint2 hi-bf16 B fragments (64KB)
#define SM_EST   65536        // est matrix: 128 rows x 520 halves (133120B)
#define EST_STRIDE 520
#define SM_SN    198656       // 512 floats: exact ||e_k||^2
#define SM_SMIN  200704       // 256 floats: per-half row min est
#define SM_SXN   201728       // 128 floats: ||x_r||^2
#define SM_SRX   202240       // 128 floats: ||x_r - xh_r||^2
#define SM_RCNT  202752       // 128 ints: per-row candidate count
#define SM_RBEST 203264       // 128 u64: per-row packed (dist,k)
#define SM_WL    204288       // 128*CAP ints (8KB)
#define SM_OVF   212480       // int: overflow flag
#define SM_SE2   212484       // int: max_k ||e-eh||^2 (bits)
#define SM_SH2   212488       // int: max_k ||eh||^2 (bits)
#define SM_LS    212496       // 16 doubles
#define SMEM_TOTAL 212624

__device__ float        g_embT[K_CODES * D_DIM];   // exact fp32 codebook [k][d]
__device__ double       g_partial[GRID];
__device__ unsigned int g_cnt = 0;

#define MMA(acc, a, b0, b1)                                                     \
    asm volatile(                                                               \
        "mma.sync.aligned.m16n8k16.row.col.f32.bf16.bf16.f32 "                  \
        "{%0,%1,%2,%3}, {%4,%5,%6,%7}, {%8,%9}, {%0,%1,%2,%3};"                 \
        : "+f"((acc)[0]), "+f"((acc)[1]), "+f"((acc)[2]), "+f"((acc)[3])        \
        : "r"((a)[0]), "r"((a)[1]), "r"((a)[2]), "r"((a)[3]), "r"(b0), "r"(b1))

__device__ __forceinline__ uint32_t pack_bf2(float a, float b) {
    return (uint32_t)__bfloat16_as_ushort(__float2bfloat16(a))
         | ((uint32_t)__bfloat16_as_ushort(__float2bfloat16(b)) << 16);
}

// exact fp32 squared distance row(x) vs code k (fixed summation order)
__device__ __forceinline__ float exact_dist(const float* __restrict__ xrow, int k) {
    const float4* xp = (const float4*)xrow;
    const float4* ep = (const float4*)(g_embT + k * D_DIM);
    float s = 0.f;
    #pragma unroll
    for (int j = 0; j < 16; j++) {
        float4 a = xp[j];
        float4 b = ep[j];
        float dx = a.x - b.x, dy = a.y - b.y, dz = a.z - b.z, dw = a.w - b.w;
        s = fmaf(dx, dx, s); s = fmaf(dy, dy, s);
        s = fmaf(dz, dz, s); s = fmaf(dw, dw, s);
    }
    return s;
}

__global__ void __launch_bounds__(BLOCK, 1)
vq_2stage(const float* __restrict__ x, const float* __restrict__ emb,
          float* __restrict__ out, int write_loss)
{
    extern __shared__ char smem[];
    uint2*              sBH   = (uint2*)(smem + SM_BH);
    __half*             sEst  = (__half*)(smem + SM_EST);
    float*              snm   = (float*)(smem + SM_SN);
    float*              smin  = (float*)(smem + SM_SMIN);
    float*              sxn   = (float*)(smem + SM_SXN);
    float*              srx   = (float*)(smem + SM_SRX);
    int*                rcnt  = (int*)(smem + SM_RCNT);
    unsigned long long* rbest = (unsigned long long*)(smem + SM_RBEST);
    int*                swl   = (int*)(smem + SM_WL);
    int*                sovf  = (int*)(smem + SM_OVF);
    int*                sSE2  = (int*)(smem + SM_SE2);
    int*                sSH2  = (int*)(smem + SM_SH2);
    double*             sls   = (double*)(smem + SM_LS);

    const int tid  = threadIdx.x;
    const int w    = tid >> 5;
    const int lane = tid & 31;
    const int g    = lane >> 2;
    const int c    = lane & 3;
    const int rg   = w & 7;      // row-group (16 rows)
    const int nh   = w >> 3;     // n-half: codes [nh*256, +256)
    const unsigned ltmask = (1u << lane) - 1u;

    if (tid < 2) { sSE2[0] = 0; sSH2[0] = 0; }
    __syncthreads();

    // ---- Prologue 1: hi-bf16 B fragments + exact fp32 transpose ----
    for (int i = tid; i < 8192; i += BLOCK) {
        int nt = i >> 7;
        int ks = (i >> 5) & 3;
        int ln = i & 31;
        int fg = ln >> 2, fc = ln & 3;
        int n  = nt * 8 + fg;
        int d0 = ks * 16 + fc * 2;
        float e00 = __ldg(emb + (d0 + 0) * K_CODES + n);
        float e01 = __ldg(emb + (d0 + 1) * K_CODES + n);
        float e10 = __ldg(emb + (d0 + 8) * K_CODES + n);
        float e11 = __ldg(emb + (d0 + 9) * K_CODES + n);
        sBH[i] = make_uint2(pack_bf2(e00, e01), pack_bf2(e10, e11));
        g_embT[n * D_DIM + d0]     = e00;
        g_embT[n * D_DIM + d0 + 1] = e01;
        g_embT[n * D_DIM + d0 + 8] = e10;
        g_embT[n * D_DIM + d0 + 9] = e11;
    }
    // ---- Prologue 2: exact code norms + split-error maxima ----
    {
        const int k = tid;   // 512 == BLOCK
        float sn = 0.f, se = 0.f, sh = 0.f;
        #pragma unroll 8
        for (int d = 0; d < D_DIM; d++) {
            float v = emb[d * K_CODES + k];
            float h = __bfloat162float(__float2bfloat16(v));
            float r = v - h;
            sn = fmaf(v, v, sn);
            se = fmaf(r, r, se);
            sh = fmaf(h, h, sh);
        }
        snm[k] = sn;
        atomicMax(sSE2, __float_as_int(se));   // nonneg: int cmp == float cmp
        atomicMax(sSH2, __float_as_int(sh));
    }
    __syncthreads();

    const float S_e = sqrtf(__int_as_float(*sSE2)) * 1.0001f;  // max ||e-eh||
    const float S_h = sqrtf(__int_as_float(*sSH2)) * 1.0001f;  // max ||eh||

    double lacc = 0.0;

    for (int tile = blockIdx.x; tile < NTILES; tile += GRID) {
        const int rbase = tile * 128 + rg * 16 + g;

        // per-tile state init (readers only after sync1/sync2)
        if (tid < 128) { rcnt[tid] = 0; rbest[tid] = ~0ull; }
        if (tid == 0) *sovf = 0;

        // ---- A fragments (hi split) + per-row norm / residual-norm ----
        uint32_t Ah[4][4];
        float xn0 = 0.f, xn1 = 0.f, rx0 = 0.f, rx1 = 0.f;
        {
            const float* xr0 = x + (size_t)rbase * D_DIM;
            const float* xr1 = xr0 + 8 * D_DIM;
            #pragma unroll
            for (int ks = 0; ks < 4; ks++) {
                #pragma unroll
                for (int p = 0; p < 2; p++) {
                    int col = 2 * c + 8 * p + 16 * ks;
                    float2 v0 = *(const float2*)(xr0 + col);
                    float2 v1 = *(const float2*)(xr1 + col);
                    xn0 = fmaf(v0.x, v0.x, fmaf(v0.y, v0.y, xn0));
                    xn1 = fmaf(v1.x, v1.x, fmaf(v1.y, v1.y, xn1));
                    float h0x = __bfloat162float(__float2bfloat16(v0.x));
                    float h0y = __bfloat162float(__float2bfloat16(v0.y));
                    float h1x = __bfloat162float(__float2bfloat16(v1.x));
                    float h1y = __bfloat162float(__float2bfloat16(v1.y));
                    float r0x = v0.x - h0x, r0y = v0.y - h0y;
                    float r1x = v1.x - h1x, r1y = v1.y - h1y;
                    rx0 = fmaf(r0x, r0x, fmaf(r0y, r0y, rx0));
                    rx1 = fmaf(r1x, r1x, fmaf(r1y, r1y, rx1));
                    Ah[ks][2 * p]     = pack_bf2(v0.x, v0.y);
                    Ah[ks][2 * p + 1] = pack_bf2(v1.x, v1.y);
                }
            }
        }
        #pragma unroll
        for (int off = 1; off <= 2; off <<= 1) {
            xn0 += __shfl_xor_sync(0xffffffffu, xn0, off);
            xn1 += __shfl_xor_sync(0xffffffffu, xn1, off);
            rx0 += __shfl_xor_sync(0xffffffffu, rx0, off);
            rx1 += __shfl_xor_sync(0xffffffffu, rx1, off);
        }
        if (c == 0 && nh == 0) {
            const int r = rg * 16 + g;
            sxn[r] = xn0;  sxn[r + 8] = xn1;
            srx[r] = rx0;  srx[r + 8] = rx1;
        }

        // ---- Stage A: estimated distances (hi-hi term), fp16 store + row min ----
        float m0 = FLT_MAX, m1 = FLT_MAX;
        const int ntbeg = nh * 32;
        #pragma unroll 1
        for (int nt0 = ntbeg; nt0 < ntbeg + 32; nt0 += 4) {
            float acc[4][4];
            #pragma unroll
            for (int u = 0; u < 4; u++)
                #pragma unroll
                for (int r = 0; r < 4; r++) acc[u][r] = 0.f;

            #pragma unroll
            for (int ks = 0; ks < 4; ks++)
                #pragma unroll
                for (int u = 0; u < 4; u++) {
                    uint2 b = sBH[((nt0 + u) * 4 + ks) * 32 + lane];
                    MMA(acc[u], Ah[ks], b.x, b.y);
                }

            #pragma unroll
            for (int u = 0; u < 4; u++) {
                const int kb = (nt0 + u) * 8 + 2 * c;
                float2 s2 = *(const float2*)(snm + kb);
                float e00 = fmaf(-2.f, acc[u][0], s2.x);
                float e01 = fmaf(-2.f, acc[u][1], s2.y);
                float e10 = fmaf(-2.f, acc[u][2], s2.x);
                float e11 = fmaf(-2.f, acc[u][3], s2.y);
                m0 = fminf(m0, fminf(e00, e01));
                m1 = fminf(m1, fminf(e10, e11));
                const int r0 = rg * 16 + g;
                *(__half2*)(sEst + r0 * EST_STRIDE + kb)       = __floats2half2_rn(e00, e01);
                *(__half2*)(sEst + (r0 + 8) * EST_STRIDE + kb) = __floats2half2_rn(e10, e11);
            }
        }
        #pragma unroll
        for (int off = 1; off <= 2; off <<= 1) {
            m0 = fminf(m0, __shfl_xor_sync(0xffffffffu, m0, off));
            m1 = fminf(m1, __shfl_xor_sync(0xffffffffu, m1, off));
        }
        if (c == 0) {
            const int r = rg * 16 + g;
            smin[nh * 128 + r]     = m0;
            smin[nh * 128 + r + 8] = m1;
        }
        __syncthreads();   // sync1: est, smin, norms, rcnt/rbest/sovf ready

        // ---- Scan: warp per row, ballots, atomic-free append via prefix ----
        #pragma unroll 1
        for (int rr = 0; rr < 8; rr++) {
            const int row = w * 8 + rr;
            float minest = fminf(smin[row], smin[128 + row]);
            float xns = sqrtf(sxn[row]), rxs = sqrtf(srx[row]);
            // rigorous: |est-true| <= 2(rxs*(S_h+S_e) + (xns+rxs)*S_e)
            float bnd  = 2.f * (rxs * (S_h + S_e) + (xns + rxs) * S_e);
            float thrf = minest + 2.f * bnd + 0.15f;
            const __half2 thr2 = __float2half2_rn(thrf + 0.05f);
            const __half2* erow = (const __half2*)(sEst + row * EST_STRIDE);
            int cnt = 0;
            #pragma unroll 1
            for (int j = 0; j < 8; j++) {
                __half2 v  = erow[j * 32 + lane];
                __half2 le = __hle2(v, thr2);
                float2  lf = __half22float2(le);
                unsigned blo = __ballot_sync(0xffffffffu, lf.x != 0.f);
                unsigned bhi = __ballot_sync(0xffffffffu, lf.y != 0.f);
                const int k0 = j * 64 + 2 * lane;
                if (blo) {
                    int pos = cnt + __popc(blo & ltmask);
                    if (((blo >> lane) & 1) && pos < CAP) swl[row * CAP + pos] = k0;
                    cnt += __popc(blo);
                }
                if (bhi) {
                    int pos = cnt + __popc(bhi & ltmask);
                    if (((bhi >> lane) & 1) && pos < CAP) swl[row * CAP + pos] = k0 + 1;
                    cnt += __popc(bhi);
                }
            }
            if (lane == 0) {
                rcnt[row] = cnt;
                if (cnt > CAP) *sovf = 1;
            }
        }
        __syncthreads();   // sync2: worklists complete

        // ---- Rescore: spread candidates over all threads, u64 atomicMin ----
        #pragma unroll
        for (int it = 0; it < (128 * CAP) / BLOCK; it++) {
            const int idx  = it * BLOCK + tid;
            const int row  = idx >> 4;           // CAP = 16
            const int slot = idx & (CAP - 1);
            int cnt = rcnt[row]; if (cnt > CAP) cnt = CAP;
            if (slot < cnt) {
                const int k = swl[row * CAP + slot];
                float s = exact_dist(x + (size_t)(tile * 128 + row) * D_DIM, k);
                unsigned long long key =
                    ((unsigned long long)(unsigned)__float_as_int(s) << 32) | (unsigned)k;
                atomicMin(&rbest[row], key);
            }
        }
        if (*sovf) {   // provably-correct fallback; practically never taken
            #pragma unroll 1
            for (int rr = 0; rr < 8; rr++) {
                const int row = w * 8 + rr;
                if (rcnt[row] > CAP) {
                    const float* xrow = x + (size_t)(tile * 128 + row) * D_DIM;
                    for (int k = lane; k < K_CODES; k += 32) {
                        float s = exact_dist(xrow, k);
                        unsigned long long key =
                            ((unsigned long long)(unsigned)__float_as_int(s) << 32) | (unsigned)k;
                        atomicMin(&rbest[row], key);
                    }
                }
            }
        }
        __syncthreads();   // sync3: rbest final

        // ---- output + loss ----
        {
            const int r = tid >> 2;
            const int q = tid & 3;
            unsigned long long key = rbest[r];
            const int k = (int)(unsigned)key;
            if (q == 0) lacc += (double)__int_as_float((int)(key >> 32));
            const float4* src = (const float4*)(g_embT + k * D_DIM) + q * 4;
            float4* dst = (float4*)(out + (size_t)(tile * 128 + r) * D_DIM) + q * 4;
            dst[0] = src[0]; dst[1] = src[1]; dst[2] = src[2]; dst[3] = src[3];
        }
        __syncthreads();   // sync4: est/rbest reused next tile
    }

    // ---- loss: warp reduce -> CTA partial -> last block finalizes ----
    #pragma unroll
    for (int off = 16; off > 0; off >>= 1)
        lacc += __shfl_down_sync(0xffffffffu, lacc, off);
    if (lane == 0) sls[w] = lacc;
    __syncthreads();
    if (tid == 0) {
        double t = 0.0;
        #pragma unroll
        for (int i = 0; i < 16; i++) t += sls[i];
        g_partial[blockIdx.x] = t;
        __threadfence();
        unsigned n = atomicAdd(&g_cnt, 1u);
        if (n == GRID - 1) {
            __threadfence();
            double tot = 0.0;
            for (int i = 0; i < GRID; i++) tot += g_partial[i];
            if (write_loss)
                out[(size_t)NROWS * D_DIM] =
                    (float)(tot * (1.25 / ((double)NROWS * (double)D_DIM)));
            g_cnt = 0;   // reset for next graph replay
        }
    }
}

extern "C" void kernel_launch(void* const* d_in, const int* in_sizes, int n_in,
                              void* d_out, int out_size)
{
    const float* x   = (const float*)d_in[0];
    const float* emb = (const float*)d_in[1];
    float* out = (float*)d_out;

    const int write_loss = (out_size > NROWS * D_DIM) ? 1 : 0;

    static int configured = 0;
    if (!configured) {
        cudaFuncSetAttribute(vq_2stage, cudaFuncAttributeMaxDynamicSharedMemorySize, SMEM_TOTAL);
        configured = 1;
    }
    vq_2stage<<<GRID, BLOCK, SMEM_TOTAL>>>(x, emb, out, write_loss);
}

// round 11
// speedup vs baseline: 1.2179x; 1.0974x over previous
#include <cuda_runtime.h>
#include <cuda_bf16.h>
#include <cuda_fp16.h>
#include <float.h>
#include <stdint.h>

#define D_DIM   64
#define K_CODES 512
#define BLOCK   512          // 16 warps: 4 row-groups x 4 code-quarters
#define GRID    148
#define NROWS   65536
#define TILE    64           // rows per tile
#define NTILES  1024
#define CAP     16           // worklist slots per row

// ---- SMEM layout (bytes) ----
#define SM_BH    0            // 8192 uint2 hi-bf16 B fragments (64KB)
#define SM_EST   65536        // est: 64 rows x 520 halves (66560B)
#define EST_STRIDE 520        // halves per row (1040B, 16B-aligned, pad vs conflicts)
#define SM_SN    132096       // 512 floats: exact ||e_k||^2
#define SM_SMIN  134144       // 4*64 floats: per-quarter row min est
#define SM_SXN   135168       // 64 floats: ||x_r||^2
#define SM_SRX   135424       // 64 floats: ||x_r - xh_r||^2
#define SM_RCNT  135680       // 64 ints
#define SM_RBEST 135936       // 64 u64 packed (dist,k)
#define SM_WL    136448       // 64*CAP ints (4KB)
#define SM_OVF   140544       // int
#define SM_SE2   140548       // int: max_k ||e-eh||^2 (bits)
#define SM_SH2   140552       // int: max_k ||eh||^2 (bits)
#define SM_LS    140560       // 16 doubles
#define SMEM_TOTAL 140688

__device__ float        g_embT[K_CODES * D_DIM];   // exact fp32 codebook [k][d]
__device__ double       g_partial[GRID];
__device__ unsigned int g_cnt = 0;

#define MMA(acc, a, b0, b1)                                                     \
    asm volatile(                                                               \
        "mma.sync.aligned.m16n8k16.row.col.f32.bf16.bf16.f32 "                  \
        "{%0,%1,%2,%3}, {%4,%5,%6,%7}, {%8,%9}, {%0,%1,%2,%3};"                 \
        : "+f"((acc)[0]), "+f"((acc)[1]), "+f"((acc)[2]), "+f"((acc)[3])        \
        : "r"((a)[0]), "r"((a)[1]), "r"((a)[2]), "r"((a)[3]), "r"(b0), "r"(b1))

__device__ __forceinline__ uint32_t pack_bf2(float a, float b) {
    return (uint32_t)__bfloat16_as_ushort(__float2bfloat16(a))
         | ((uint32_t)__bfloat16_as_ushort(__float2bfloat16(b)) << 16);
}

// exact fp32 squared distance row(x) vs code k (fixed summation order)
__device__ __forceinline__ float exact_dist(const float* __restrict__ xrow, int k) {
    const float4* xp = (const float4*)xrow;
    const float4* ep = (const float4*)(g_embT + k * D_DIM);
    float s = 0.f;
    #pragma unroll
    for (int j = 0; j < 16; j++) {
        float4 a = xp[j];
        float4 b = ep[j];
        float dx = a.x - b.x, dy = a.y - b.y, dz = a.z - b.z, dw = a.w - b.w;
        s = fmaf(dx, dx, s); s = fmaf(dy, dy, s);
        s = fmaf(dz, dz, s); s = fmaf(dw, dw, s);
    }
    return s;
}

// test one half2 of estimates vs threshold, append passing codes (rare path)
__device__ __forceinline__ void test_h2(uint32_t h2bits, __half2 thr2, int kbase,
                                        int row, int* rcnt, int* swl) {
    __half2 v  = *(__half2*)&h2bits;
    __half2 le = __hle2(v, thr2);
    uint32_t m = *(uint32_t*)&le;
    if (m) {
        if (m & 0xFFFFu) {
            int s = atomicAdd(&rcnt[row], 1);
            if (s < CAP) swl[row * CAP + s] = kbase;
        }
        if (m >> 16) {
            int s = atomicAdd(&rcnt[row], 1);
            if (s < CAP) swl[row * CAP + s] = kbase + 1;
        }
    }
}

__global__ void __launch_bounds__(BLOCK, 1)
vq_2stage(const float* __restrict__ x, const float* __restrict__ emb,
          float* __restrict__ out, int write_loss)
{
    extern __shared__ char smem[];
    uint2*              sBH   = (uint2*)(smem + SM_BH);
    __half*             sEst  = (__half*)(smem + SM_EST);
    float*              snm   = (float*)(smem + SM_SN);
    float*              smin  = (float*)(smem + SM_SMIN);
    float*              sxn   = (float*)(smem + SM_SXN);
    float*              srx   = (float*)(smem + SM_SRX);
    int*                rcnt  = (int*)(smem + SM_RCNT);
    unsigned long long* rbest = (unsigned long long*)(smem + SM_RBEST);
    int*                swl   = (int*)(smem + SM_WL);
    int*                sovf  = (int*)(smem + SM_OVF);
    int*                sSE2  = (int*)(smem + SM_SE2);
    int*                sSH2  = (int*)(smem + SM_SH2);
    double*             sls   = (double*)(smem + SM_LS);

    const int tid  = threadIdx.x;
    const int w    = tid >> 5;
    const int lane = tid & 31;
    const int g    = lane >> 2;
    const int c    = lane & 3;
    const int rg   = w & 3;      // row-group (16 rows)
    const int nq   = w >> 2;     // code-quarter: [nq*128, +128)

    if (tid < 2) { sSE2[0] = 0; sSH2[0] = 0; }
    __syncthreads();

    // ---- Prologue 1: hi-bf16 B fragments + exact fp32 transpose ----
    for (int i = tid; i < 8192; i += BLOCK) {
        int nt = i >> 7;
        int ks = (i >> 5) & 3;
        int ln = i & 31;
        int fg = ln >> 2, fc = ln & 3;
        int n  = nt * 8 + fg;
        int d0 = ks * 16 + fc * 2;
        float e00 = __ldg(emb + (d0 + 0) * K_CODES + n);
        float e01 = __ldg(emb + (d0 + 1) * K_CODES + n);
        float e10 = __ldg(emb + (d0 + 8) * K_CODES + n);
        float e11 = __ldg(emb + (d0 + 9) * K_CODES + n);
        sBH[i] = make_uint2(pack_bf2(e00, e01), pack_bf2(e10, e11));
        g_embT[n * D_DIM + d0]     = e00;
        g_embT[n * D_DIM + d0 + 1] = e01;
        g_embT[n * D_DIM + d0 + 8] = e10;
        g_embT[n * D_DIM + d0 + 9] = e11;
    }
    // ---- Prologue 2: exact code norms + split-error maxima ----
    {
        const int k = tid;   // 512 == BLOCK
        float sn = 0.f, se = 0.f, sh = 0.f;
        #pragma unroll 8
        for (int d = 0; d < D_DIM; d++) {
            float v = emb[d * K_CODES + k];
            float h = __bfloat162float(__float2bfloat16(v));
            float r = v - h;
            sn = fmaf(v, v, sn);
            se = fmaf(r, r, se);
            sh = fmaf(h, h, sh);
        }
        snm[k] = sn;
        atomicMax(sSE2, __float_as_int(se));   // nonneg: int cmp == float cmp
        atomicMax(sSH2, __float_as_int(sh));
    }
    __syncthreads();

    const float S_e = sqrtf(__int_as_float(*sSE2)) * 1.0001f;  // max ||e-eh||
    const float S_h = sqrtf(__int_as_float(*sSH2)) * 1.0001f;  // max ||eh||

    double lacc = 0.0;

    for (int tile = blockIdx.x; tile < NTILES; tile += GRID) {
        const int rbase = tile * TILE + rg * 16 + g;

        // per-tile state init (readers only after sync1/sync2)
        if (tid < TILE) { rcnt[tid] = 0; rbest[tid] = ~0ull; }
        if (tid == 0) *sovf = 0;

        // ---- A fragments (hi split) + per-row norm / residual-norm ----
        uint32_t Ah[4][4];
        float xn0 = 0.f, xn1 = 0.f, rx0 = 0.f, rx1 = 0.f;
        {
            const float* xr0 = x + (size_t)rbase * D_DIM;
            const float* xr1 = xr0 + 8 * D_DIM;
            #pragma unroll
            for (int ks = 0; ks < 4; ks++) {
                #pragma unroll
                for (int p = 0; p < 2; p++) {
                    int col = 2 * c + 8 * p + 16 * ks;
                    float2 v0 = *(const float2*)(xr0 + col);
                    float2 v1 = *(const float2*)(xr1 + col);
                    xn0 = fmaf(v0.x, v0.x, fmaf(v0.y, v0.y, xn0));
                    xn1 = fmaf(v1.x, v1.x, fmaf(v1.y, v1.y, xn1));
                    float h0x = __bfloat162float(__float2bfloat16(v0.x));
                    float h0y = __bfloat162float(__float2bfloat16(v0.y));
                    float h1x = __bfloat162float(__float2bfloat16(v1.x));
                    float h1y = __bfloat162float(__float2bfloat16(v1.y));
                    float r0x = v0.x - h0x, r0y = v0.y - h0y;
                    float r1x = v1.x - h1x, r1y = v1.y - h1y;
                    rx0 = fmaf(r0x, r0x, fmaf(r0y, r0y, rx0));
                    rx1 = fmaf(r1x, r1x, fmaf(r1y, r1y, rx1));
                    Ah[ks][2 * p]     = pack_bf2(v0.x, v0.y);
                    Ah[ks][2 * p + 1] = pack_bf2(v1.x, v1.y);
                }
            }
        }
        #pragma unroll
        for (int off = 1; off <= 2; off <<= 1) {
            xn0 += __shfl_xor_sync(0xffffffffu, xn0, off);
            xn1 += __shfl_xor_sync(0xffffffffu, xn1, off);
            rx0 += __shfl_xor_sync(0xffffffffu, rx0, off);
            rx1 += __shfl_xor_sync(0xffffffffu, rx1, off);
        }
        if (c == 0 && nq == 0) {
            const int r = rg * 16 + g;
            sxn[r] = xn0;  sxn[r + 8] = xn1;
            srx[r] = rx0;  srx[r + 8] = rx1;
        }

        // ---- Stage A: estimated distances (hi-hi term), fp16 store + row min ----
        float m0 = FLT_MAX, m1 = FLT_MAX;
        const int ntbeg = nq * 16;
        #pragma unroll 1
        for (int nt0 = ntbeg; nt0 < ntbeg + 16; nt0 += 4) {
            float acc[4][4];
            #pragma unroll
            for (int u = 0; u < 4; u++)
                #pragma unroll
                for (int r = 0; r < 4; r++) acc[u][r] = 0.f;

            #pragma unroll
            for (int ks = 0; ks < 4; ks++)
                #pragma unroll
                for (int u = 0; u < 4; u++) {
                    uint2 b = sBH[((nt0 + u) * 4 + ks) * 32 + lane];
                    MMA(acc[u], Ah[ks], b.x, b.y);
                }

            #pragma unroll
            for (int u = 0; u < 4; u++) {
                const int kb = (nt0 + u) * 8 + 2 * c;
                float2 s2 = *(const float2*)(snm + kb);
                float e00 = fmaf(-2.f, acc[u][0], s2.x);
                float e01 = fmaf(-2.f, acc[u][1], s2.y);
                float e10 = fmaf(-2.f, acc[u][2], s2.x);
                float e11 = fmaf(-2.f, acc[u][3], s2.y);
                m0 = fminf(m0, fminf(e00, e01));
                m1 = fminf(m1, fminf(e10, e11));
                const int r0 = rg * 16 + g;
                *(__half2*)(sEst + r0 * EST_STRIDE + kb)       = __floats2half2_rn(e00, e01);
                *(__half2*)(sEst + (r0 + 8) * EST_STRIDE + kb) = __floats2half2_rn(e10, e11);
            }
        }
        #pragma unroll
        for (int off = 1; off <= 2; off <<= 1) {
            m0 = fminf(m0, __shfl_xor_sync(0xffffffffu, m0, off));
            m1 = fminf(m1, __shfl_xor_sync(0xffffffffu, m1, off));
        }
        if (c == 0) {
            const int r = rg * 16 + g;
            smin[nq * TILE + r]     = m0;
            smin[nq * TILE + r + 8] = m1;
        }
        __syncthreads();   // sync1: est, smin, norms, state ready

        // ---- Scan: warp per row (4 rows/warp), vectorized rare-path test ----
        #pragma unroll 1
        for (int rr = 0; rr < 4; rr++) {
            const int row = w * 4 + rr;
            float minest = fminf(fminf(smin[row], smin[TILE + row]),
                                 fminf(smin[2 * TILE + row], smin[3 * TILE + row]));
            float xns = sqrtf(sxn[row]), rxs = sqrtf(srx[row]);
            // rigorous: |est-true| <= 2(rxs*(S_h+S_e) + (xns+rxs)*S_e)
            float bnd  = 2.f * (rxs * (S_h + S_e) + (xns + rxs) * S_e);
            float thrf = minest + 2.f * bnd + 0.15f;
            const __half2 thr2 = __float2half2_rn(thrf + 0.05f);   // round-up guard
            const uint4* erow4 = (const uint4*)(sEst + row * EST_STRIDE);
            #pragma unroll
            for (int part = 0; part < 2; part++) {
                const int jj = part * 32 + lane;        // uint4 idx: codes 8jj..8jj+7
                uint4 v = erow4[jj];
                // cheap any-pass check first (candidates are rare)
                __half2 t0 = __hle2(*(__half2*)&v.x, thr2);
                __half2 t1 = __hle2(*(__half2*)&v.y, thr2);
                __half2 t2 = __hle2(*(__half2*)&v.z, thr2);
                __half2 t3 = __hle2(*(__half2*)&v.w, thr2);
                uint32_t any = *(uint32_t*)&t0 | *(uint32_t*)&t1
                             | *(uint32_t*)&t2 | *(uint32_t*)&t3;
                if (any) {
                    const int k0 = jj * 8;
                    test_h2(v.x, thr2, k0,     row, rcnt, swl);
                    test_h2(v.y, thr2, k0 + 2, row, rcnt, swl);
                    test_h2(v.z, thr2, k0 + 4, row, rcnt, swl);
                    test_h2(v.w, thr2, k0 + 6, row, rcnt, swl);
                }
            }
        }
        __syncthreads();   // sync2: worklists complete

        // ---- Rescore: spread candidates over all threads, u64 atomicMin ----
        #pragma unroll
        for (int it = 0; it < (TILE * CAP) / BLOCK; it++) {
            const int idx  = it * BLOCK + tid;
            const int row  = idx >> 4;           // CAP = 16
            const int slot = idx & (CAP - 1);
            int cnt = rcnt[row]; if (cnt > CAP) cnt = CAP;
            if (slot < cnt) {
                const int k = swl[row * CAP + slot];
                float s = exact_dist(x + (size_t)(tile * TILE + row) * D_DIM, k);
                unsigned long long key =
                    ((unsigned long long)(unsigned)__float_as_int(s) << 32) | (unsigned)k;
                atomicMin(&rbest[row], key);
            }
        }
        if (*sovf == 0) {
            // fast path: nothing overflowed (checked below); but flag is set in scan?
        }
        // overflow detection + provably-correct fallback (practically never taken)
        #pragma unroll 1
        for (int rr = 0; rr < 4; rr++) {
            const int row = w * 4 + rr;
            if (rcnt[row] > CAP) {
                const float* xrow = x + (size_t)(tile * TILE + row) * D_DIM;
                for (int k = lane; k < K_CODES; k += 32) {
                    float s = exact_dist(xrow, k);
                    unsigned long long key =
                        ((unsigned long long)(unsigned)__float_as_int(s) << 32) | (unsigned)k;
                    atomicMin(&rbest[row], key);
                }
            }
        }
        __syncthreads();   // sync3: rbest final

        // ---- output + loss: 8 threads per row, 2 float4 each ----
        {
            const int r = tid >> 3;              // 0..63
            const int q = tid & 7;
            unsigned long long key = rbest[r];
            const int k = (int)(unsigned)key;
            if (q == 0) lacc += (double)__int_as_float((int)(key >> 32));
            const float4* src = (const float4*)(g_embT + k * D_DIM);
            float4* dst = (float4*)(out + (size_t)(tile * TILE + r) * D_DIM);
            dst[q]     = src[q];
            dst[q + 8] = src[q + 8];
        }
        __syncthreads();   // sync4: est/rbest reused next tile
    }

    // ---- loss: warp reduce -> CTA partial -> last block finalizes ----
    #pragma unroll
    for (int off = 16; off > 0; off >>= 1)
        lacc += __shfl_down_sync(0xffffffffu, lacc, off);
    if (lane == 0) sls[w] = lacc;
    __syncthreads();
    if (tid == 0) {
        double t = 0.0;
        #pragma unroll
        for (int i = 0; i < 16; i++) t += sls[i];
        g_partial[blockIdx.x] = t;
        __threadfence();
        unsigned n = atomicAdd(&g_cnt, 1u);
        if (n == GRID - 1) {
            __threadfence();
            double tot = 0.0;
            for (int i = 0; i < GRID; i++) tot += g_partial[i];
            if (write_loss)
                out[(size_t)NROWS * D_DIM] =
                    (float)(tot * (1.25 / ((double)NROWS * (double)D_DIM)));
            g_cnt = 0;   // reset for next graph replay
        }
    }
}

extern "C" void kernel_launch(void* const* d_in, const int* in_sizes, int n_in,
                              void* d_out, int out_size)
{
    const float* x   = (const float*)d_in[0];
    const float* emb = (const float*)d_in[1];
    float* out = (float*)d_out;

    const int write_loss = (out_size > NROWS * D_DIM) ? 1 : 0;

    static int configured = 0;
    if (!configured) {
        cudaFuncSetAttribute(vq_2stage, cudaFuncAttributeMaxDynamicSharedMemorySize, SMEM_TOTAL);
        configured = 1;
    }
    vq_2stage<<<GRID, BLOCK, SMEM_TOTAL>>>(x, emb, out, write_loss);
}